// round 11
// baseline (speedup 1.0000x reference)
#include <cuda_runtime.h>
#include <cstdint>
#include <math.h>

// ---------------------------------------------------------------------------
// Problem dims
// ---------------------------------------------------------------------------
#define B_DIM 32
#define T_DIM 512
#define K_DIM 1024
#define N_DIM 1024
#define M_DIM (B_DIM * T_DIM)   // 16384

// ---------------------------------------------------------------------------
// Static device scratch (allocation-guard safe)
// ---------------------------------------------------------------------------
__device__ float g_Y[(size_t)M_DIM * N_DIM];   // 64 MB pre-activations

// ---------------------------------------------------------------------------
// SGEMM: Y[m][n] = sum_k X[m][k] * W[n][k]   (serial-k fp32, bitwise-exact)
// 128x128 tile, BK=32 (halved barrier count vs R8), 256 threads,
// 8x8 per thread via fma.rn.f32x2, row-paired accumulators (R8 scheme).
// Dynamic smem: 2 bufs x (A + B) x 32 x 132 floats = 67584 B, 2 CTAs/SM.
// ---------------------------------------------------------------------------
#define BM 128
#define BN 128
#define BK 32
#define PAD 132    // row stride in floats

#define BUF_F (BK * PAD)                 // 4224 floats per matrix per buffer
#define SMEM_FLOATS (4 * BUF_F)          // As0|As1|Bs0|Bs1
#define SMEM_BYTES (SMEM_FLOATS * 4)     // 67584

__global__ void __launch_bounds__(256, 2)
gemm_kernel(const float* __restrict__ A,      // [M_DIM, K_DIM]
            const float* __restrict__ W)      // [N_DIM, K_DIM]
{
    extern __shared__ __align__(16) float smem[];
    float* As0 = smem;
    float* As1 = smem + BUF_F;
    float* Bs0 = smem + 2 * BUF_F;
    float* Bs1 = smem + 3 * BUF_F;

    const int bm = blockIdx.y * BM;
    const int bn = blockIdx.x * BN;
    const int tid = threadIdx.x;

    // load mapping: 2 threads per row; each thread 4 float4 (16 k) of A and W
    const int lrow = tid >> 1;             // 0..127
    const int lk16 = (tid & 1) << 4;       // 0 or 16

    // compute mapping: 16x16 threads, 8x8 each
    const int ty = tid >> 4;               // 0..15
    const int tx = tid & 15;               // 0..15

    const float* Arow = A + (size_t)(bm + lrow) * K_DIM + lk16;
    const float* Wrow = W + (size_t)(bn + lrow) * K_DIM + lk16;

    // row-paired accumulators (see R8)
    unsigned long long acc2[4][8];
#pragma unroll
    for (int ip = 0; ip < 4; ip++)
#pragma unroll
        for (int j = 0; j < 8; j++) acc2[ip][j] = 0ULL;

    float4 sa[4], sw[4];

    auto ldg_chunk = [&](int k0) {
#pragma unroll
        for (int i = 0; i < 4; i++) {
            sa[i] = *(const float4*)(Arow + k0 + 4 * i);
            sw[i] = *(const float4*)(Wrow + k0 + 4 * i);
        }
    };

    auto sts_chunk = [&](float* As, float* Bs) {
#pragma unroll
        for (int i = 0; i < 4; i++) {
            const int kb = lk16 + 4 * i;
            As[(kb + 0) * PAD + lrow] = sa[i].x;
            As[(kb + 1) * PAD + lrow] = sa[i].y;
            As[(kb + 2) * PAD + lrow] = sa[i].z;
            As[(kb + 3) * PAD + lrow] = sa[i].w;
            Bs[(kb + 0) * PAD + lrow] = sw[i].x;
            Bs[(kb + 1) * PAD + lrow] = sw[i].y;
            Bs[(kb + 2) * PAD + lrow] = sw[i].z;
            Bs[(kb + 3) * PAD + lrow] = sw[i].w;
        }
    };

    auto compute = [&](const float* As, const float* Bs) {
#pragma unroll
        for (int kk = 0; kk < BK; kk++) {
            ulonglong2 ap0 = *(const ulonglong2*)&As[kk * PAD + 4 * ty];
            ulonglong2 ap1 = *(const ulonglong2*)&As[kk * PAD + 64 + 4 * ty];
            float4 bv0 = *(const float4*)&Bs[kk * PAD + 4 * tx];
            float4 bv1 = *(const float4*)&Bs[kk * PAD + 64 + 4 * tx];

            unsigned long long a2[4] = {ap0.x, ap0.y, ap1.x, ap1.y};

            unsigned long long b2[8];
            asm("mov.b64 %0, {%1,%1};" : "=l"(b2[0]) : "f"(bv0.x));
            asm("mov.b64 %0, {%1,%1};" : "=l"(b2[1]) : "f"(bv0.y));
            asm("mov.b64 %0, {%1,%1};" : "=l"(b2[2]) : "f"(bv0.z));
            asm("mov.b64 %0, {%1,%1};" : "=l"(b2[3]) : "f"(bv0.w));
            asm("mov.b64 %0, {%1,%1};" : "=l"(b2[4]) : "f"(bv1.x));
            asm("mov.b64 %0, {%1,%1};" : "=l"(b2[5]) : "f"(bv1.y));
            asm("mov.b64 %0, {%1,%1};" : "=l"(b2[6]) : "f"(bv1.z));
            asm("mov.b64 %0, {%1,%1};" : "=l"(b2[7]) : "f"(bv1.w));

#pragma unroll
            for (int ip = 0; ip < 4; ip++)
#pragma unroll
                for (int j = 0; j < 8; j++)
                    asm("fma.rn.f32x2 %0, %1, %2, %0;"
                        : "+l"(acc2[ip][j]) : "l"(a2[ip]), "l"(b2[j]));
        }
    };

    // prologue
    ldg_chunk(0);
    sts_chunk(As0, Bs0);
    __syncthreads();

    const int NCHUNK = K_DIM / BK;      // 32
    for (int c = 0; c < NCHUNK; c++) {
        const bool even = !(c & 1);
        if (c + 1 < NCHUNK) ldg_chunk((c + 1) * BK);

        compute(even ? As0 : As1, even ? Bs0 : Bs1);

        if (c + 1 < NCHUNK) {
            sts_chunk(even ? As1 : As0, even ? Bs1 : Bs0);
            __syncthreads();
        }
    }

    // epilogue: unpack row-pairs and store float4 per row
#pragma unroll
    for (int ip = 0; ip < 4; ip++) {
        const int rbase = bm + ((ip < 2) ? (ty * 4 + 2 * ip) : (64 + ty * 4 + 2 * (ip - 2)));
        float lo[8], hi[8];
#pragma unroll
        for (int j = 0; j < 8; j++)
            asm("mov.b64 {%0,%1}, %2;" : "=f"(lo[j]), "=f"(hi[j]) : "l"(acc2[ip][j]));
#pragma unroll
        for (int jb = 0; jb < 2; jb++) {
            const int ccol = bn + jb * 64 + tx * 4;
            float4 v0 = make_float4(lo[jb * 4 + 0], lo[jb * 4 + 1], lo[jb * 4 + 2], lo[jb * 4 + 3]);
            float4 v1 = make_float4(hi[jb * 4 + 0], hi[jb * 4 + 1], hi[jb * 4 + 2], hi[jb * 4 + 3]);
            *(float4*)(g_Y + (size_t)rbase * N_DIM + ccol) = v0;
            *(float4*)(g_Y + (size_t)(rbase + 1) * N_DIM + ccol) = v1;
        }
    }
}

// ---------------------------------------------------------------------------
// Membrane scan with fused bias. 1 float/thread (32768 threads), unroll 16.
// ---------------------------------------------------------------------------
__global__ void __launch_bounds__(256)
scan_kernel(const float* __restrict__ bias, float* __restrict__ out)
{
    const int idx = blockIdx.x * blockDim.x + threadIdx.x;   // 0..32767
    const int b = idx >> 10;
    const int n = idx & 1023;

    const float* yp = g_Y + ((size_t)b * T_DIM) * N_DIM + n;
    float* op = out + (size_t)b * N_DIM + n;
    const float bv = bias[n];

    const float f = (float)exp(-0.01);
    const float omf = 1.0f - f;

    float v = 0.0f;

    for (int t = 0; t < T_DIM; t += 16) {
        float y[16];
#pragma unroll
        for (int j = 0; j < 16; j++)
            y[j] = yp[(size_t)(t + j) * N_DIM];
#pragma unroll
        for (int j = 0; j < 16; j++) {
            float yy = y[j] + bv;
            v = f * v + omf * yy;
            float s = (v >= 1.0f) ? 1.0f : 0.0f;
            v = (s != 0.0f) ? 0.0f : v;
            op[(size_t)(t + j) * ((size_t)B_DIM * N_DIM)] = s;
        }
    }
}

// ---------------------------------------------------------------------------
extern "C" void kernel_launch(void* const* d_in, const int* in_sizes, int n_in,
                              void* d_out, int out_size)
{
    const float* x    = (const float*)d_in[0];   // [B, T, 1024]
    const float* W    = (const float*)d_in[1];   // [1024, 1024]
    const float* bias = (const float*)d_in[2];   // [1024]
    float* out        = (float*)d_out;           // [T, B, 1024]

    cudaFuncSetAttribute(gemm_kernel,
                         cudaFuncAttributeMaxDynamicSharedMemorySize, SMEM_BYTES);

    dim3 grid(N_DIM / BN, M_DIM / BM);           // (8, 128) = 1024 CTAs
    gemm_kernel<<<grid, 256, SMEM_BYTES>>>(x, W);

    scan_kernel<<<(B_DIM * N_DIM) / 256, 256>>>(bias, out);
}